// round 6
// baseline (speedup 1.0000x reference)
#include <cuda_runtime.h>
#include <cuda_bf16.h>
#include <cstdint>

#define NB 65536
#define FEAT 261
#define HID 128
#define KSTEPS 17                  // K padded to 272
#define NTILES 17                  // 136 cols: 128 Wc1 + 7 gates + 1 pad
#define NTHREAD 256
#define ROWS_BLK 64
#define NBLOCKS (NB / ROWS_BLK)    // 1024
#define GRID 444                   // 3 CTAs/SM x 148 SMs

// W fragment scratch: [kstep][tile][lane][4 u32 = bh0,bh1,bl0,bl1]
#define WFRAG_U32 (KSTEPS * NTILES * 32 * 4)   // 36992
__device__ __align__(16) uint32_t g_wfrag[WFRAG_U32];
__device__ int g_ctr;

// ---- smem layout ----
#define P_W0   0      // 288
#define P_W1   288    // 266 (pad 268)
#define P_W2   556    // 276
#define P_LEAF 832    // 64
#define P_BC1  896    // 128
#define P_WC2  1024   // 128
#define P_B    1152   // b0, b1[2], b2[4], bc2
#define P_VBUF 1160   // 2 x 64
#define P_GBUF 1288   // 64 x 8
#define PARAM_FLOATS 1800
#define OFF_BSTG (PARAM_FLOATS * 4)            // 7200, 16B aligned
#define BSTG_U4  (NTILES * 32)                 // 544 uint4 per kstep
#define SMEM_BYTES (OFF_BSTG + 2 * BSTG_U4 * 16)   // 24608

// ======================= prep: extended W -> interleaved bf16 hi/lo fragments =======================
__device__ __forceinline__ float wgate_val(int j, int k, const float* w0,
                                           const float* w1, const float* w2) {
    if (k >= FEAT) return 0.0f;
    if (j == 0) return w0[k];
    if (j < 3) {
        int nd = j - 1;
        if (k < 5) return w1[nd * 133 + k];
        int lo = 5 + nd * 128;
        if (k >= lo && k < lo + 128) return w1[nd * 133 + 5 + (k - lo)];
        return 0.0f;
    }
    if (j < 7) {
        int nd = j - 3;
        if (k < 5) return w2[nd * 69 + k];
        int lo = 5 + nd * 64;
        if (k >= lo && k < lo + 64) return w2[nd * 69 + 5 + (k - lo)];
        return 0.0f;
    }
    return 0.0f;
}

__global__ void __launch_bounds__(256) prep_w(const float* __restrict__ Wc1,
                                              const float* __restrict__ w0,
                                              const float* __restrict__ w1,
                                              const float* __restrict__ w2) {
    if (blockIdx.x == 0 && threadIdx.x == 0) g_ctr = 0;
    int idx = blockIdx.x * 256 + threadIdx.x;
    if (idx >= WFRAG_U32) return;
    int j    = idx & 3;            // 0,1: hi (b0,b1); 2,3: lo (b0,b1)
    int lane = (idx >> 2) & 31;
    int tt   = (idx >> 7) % NTILES;
    int s    = (idx >> 7) / NTILES;
    int n = tt * 8 + (lane >> 2);
    int k = s * 16 + (j & 1) * 8 + (lane & 3) * 2;

    float v0, v1;
    if (n < HID) {
        v0 = (k     < FEAT) ? Wc1[k * HID + n]       : 0.0f;
        v1 = (k + 1 < FEAT) ? Wc1[(k + 1) * HID + n] : 0.0f;
    } else {
        int jc = n - HID;
        v0 = wgate_val(jc, k,     w0, w1, w2);
        v1 = wgate_val(jc, k + 1, w0, w1, w2);
    }
    __nv_bfloat16 h0 = __float2bfloat16(v0), h1 = __float2bfloat16(v1);
    if (j < 2) {
        g_wfrag[idx] = ((uint32_t)__bfloat16_as_ushort(h1) << 16) | __bfloat16_as_ushort(h0);
    } else {
        __nv_bfloat16 l0 = __float2bfloat16(v0 - __bfloat162float(h0));
        __nv_bfloat16 l1 = __float2bfloat16(v1 - __bfloat162float(h1));
        g_wfrag[idx] = ((uint32_t)__bfloat16_as_ushort(l1) << 16) | __bfloat16_as_ushort(l0);
    }
}

// ======================= helpers =======================
__device__ __forceinline__ float sigmoidf_fast(float g) { return 1.0f / (1.0f + __expf(-g)); }

__device__ __forceinline__ uint32_t split_pair(float v0, float v1, uint32_t& lo) {
    uint32_t b0 = __float_as_uint(v0), b1 = __float_as_uint(v1), hi;
    asm("prmt.b32 %0, %1, %2, 0x7632;" : "=r"(hi) : "r"(b0), "r"(b1));
    float t0 = __uint_as_float(b0 & 0xFFFF0000u);
    float t1 = __uint_as_float(b1 & 0xFFFF0000u);
    float l0 = v0 - t0, l1 = v1 - t1;
    asm("cvt.rn.bf16x2.f32 %0, %1, %2;" : "=r"(lo) : "f"(l1), "f"(l0));
    return hi;
}

#define MMA16816(c, a0, a1, a2, a3, b0, b1) \
    asm volatile("mma.sync.aligned.m16n8k16.row.col.f32.bf16.bf16.f32 " \
        "{%0,%1,%2,%3}, {%4,%5,%6,%7}, {%8,%9}, {%0,%1,%2,%3};" \
        : "+f"((c)[0]), "+f"((c)[1]), "+f"((c)[2]), "+f"((c)[3]) \
        : "r"(a0), "r"(a1), "r"(a2), "r"(a3), "r"(b0), "r"(b1))

// ======================= main fused kernel =======================
__global__ void __launch_bounds__(NTHREAD, 3)
ac_main(const float* __restrict__ x,
        const float* __restrict__ w0, const float* __restrict__ b0,
        const float* __restrict__ w1, const float* __restrict__ b1,
        const float* __restrict__ w2, const float* __restrict__ b2,
        const float* __restrict__ leaf,
        const float* __restrict__ bc1,
        const float* __restrict__ Wc2, const float* __restrict__ bc2,
        float* __restrict__ p_out, float* __restrict__ v_out)
{
    extern __shared__ char smem[];
    float* sp = (float*)smem;
    uint4* bstg = (uint4*)(smem + OFF_BSTG);
    const int tid  = threadIdx.x;
    const int lane = tid & 31;
    const int warp = tid >> 5;
    const int mt   = warp >> 1;     // m-tile 0..3
    const int nh   = warp & 1;      // n-half

    // ---- stage params ----
    for (int i = tid; i < 288; i += NTHREAD) sp[P_W0 + i] = (i < FEAT) ? w0[i] : 0.0f;
    for (int i = tid; i < 266; i += NTHREAD) sp[P_W1 + i] = w1[i];
    for (int i = tid; i < 276; i += NTHREAD) sp[P_W2 + i] = w2[i];
    if (tid < 64)  sp[P_LEAF + tid] = leaf[tid];
    if (tid < 128) sp[P_BC1 + tid]  = bc1[tid];
    if (tid < 128) sp[P_WC2 + tid]  = Wc2[tid];
    if (tid == 0) {
        sp[P_B + 0] = b0[0];
        sp[P_B + 1] = b1[0]; sp[P_B + 2] = b1[1];
        sp[P_B + 3] = b2[0]; sp[P_B + 4] = b2[1]; sp[P_B + 5] = b2[2]; sp[P_B + 6] = b2[3];
        sp[P_B + 7] = bc2[0];
    }

    __shared__ int s_blk;
    const uint4* wsrc = (const uint4*)g_wfrag;
    const int kb = (lane & 3) * 2;

    for (;;) {
        if (tid == 0) s_blk = atomicAdd(&g_ctr, 1);
        __syncthreads();
        const int blk = s_blk;
        if (blk >= NBLOCKS) break;
        const int row0 = blk * ROWS_BLK;

        const float* xr  = x + (size_t)(row0 + mt * 16 + (lane >> 2)) * FEAT;
        const float* xr8 = xr + (size_t)8 * FEAT;

        float acc[9][4];
        #pragma unroll
        for (int t = 0; t < 9; t++)
            #pragma unroll
            for (int j = 0; j < 4; j++) acc[t][j] = 0.0f;

        // prologue: stage kstep 0, load+convert A(0)
        for (int i = tid; i < BSTG_U4; i += NTHREAD) bstg[i] = wsrc[i];
        uint32_t ah[4], al[4];
        {
            const int k0 = kb;
            float a0 = xr[k0],  a1 = xr[k0+1],  a2 = xr8[k0],  a3 = xr8[k0+1];
            float a4 = xr[k0+8], a5 = xr[k0+9], a6 = xr8[k0+8], a7 = xr8[k0+9];
            ah[0] = split_pair(a0, a1, al[0]);
            ah[1] = split_pair(a2, a3, al[1]);
            ah[2] = split_pair(a4, a5, al[2]);
            ah[3] = split_pair(a6, a7, al[3]);
        }
        __syncthreads();

        #pragma unroll 1
        for (int s = 0; s < KSTEPS; s++) {
            float af[8];
            if (s < KSTEPS - 1) {
                // stage next kstep's B fragments
                const uint4* src = wsrc + (s + 1) * BSTG_U4;
                uint4* dst = bstg + ((s + 1) & 1) * BSTG_U4;
                for (int i = tid; i < BSTG_U4; i += NTHREAD) dst[i] = src[i];
                // prefetch next A
                const int k0 = (s + 1) * 16 + kb;
                if (s + 1 < KSTEPS - 1) {
                    af[0]=xr[k0];   af[1]=xr[k0+1];  af[2]=xr8[k0];   af[3]=xr8[k0+1];
                    af[4]=xr[k0+8]; af[5]=xr[k0+9];  af[6]=xr8[k0+8]; af[7]=xr8[k0+9];
                } else {
                    af[0]=(k0  <FEAT)?xr[k0]  :0.0f; af[1]=(k0+1<FEAT)?xr[k0+1]:0.0f;
                    af[2]=(k0  <FEAT)?xr8[k0] :0.0f; af[3]=(k0+1<FEAT)?xr8[k0+1]:0.0f;
                    af[4]=(k0+8<FEAT)?xr[k0+8]:0.0f; af[5]=(k0+9<FEAT)?xr[k0+9]:0.0f;
                    af[6]=(k0+8<FEAT)?xr8[k0+8]:0.0f; af[7]=(k0+9<FEAT)?xr8[k0+9]:0.0f;
                }
            }

            const uint4* bp = bstg + (s & 1) * BSTG_U4 + nh * 8 * 32 + lane;
            #pragma unroll
            for (int i = 0; i < 8; i++) {
                const uint4 b = bp[i * 32];
                MMA16816(acc[i], ah[0], ah[1], ah[2], ah[3], b.x, b.y);
                MMA16816(acc[i], al[0], al[1], al[2], al[3], b.x, b.y);
                MMA16816(acc[i], ah[0], ah[1], ah[2], ah[3], b.z, b.w);
            }
            {   // gates tile (t = 16), all warps
                const uint4 b = bstg[(s & 1) * BSTG_U4 + 16 * 32 + lane];
                MMA16816(acc[8], ah[0], ah[1], ah[2], ah[3], b.x, b.y);
                MMA16816(acc[8], al[0], al[1], al[2], al[3], b.x, b.y);
                MMA16816(acc[8], ah[0], ah[1], ah[2], ah[3], b.z, b.w);
            }

            if (s < KSTEPS - 1) {
                #pragma unroll
                for (int p = 0; p < 4; p++)
                    ah[p] = split_pair(af[p*2], af[p*2+1], al[p]);
            }
            __syncthreads();
        }

        // ---- GEMM epilogue: v partials + gate buffer ----
        {
            float p0 = 0.0f, p1 = 0.0f;
            #pragma unroll
            for (int t = 0; t < 8; t++) {
                const int c0 = nh * 64 + t * 8 + (lane & 3) * 2;
                const float b0v = sp[P_BC1 + c0],     w0v = sp[P_WC2 + c0];
                const float b1v = sp[P_BC1 + c0 + 1], w1v = sp[P_WC2 + c0 + 1];
                p0 = fmaf(fmaxf(acc[t][0] + b0v, 0.0f), w0v, p0);
                p0 = fmaf(fmaxf(acc[t][1] + b1v, 0.0f), w1v, p0);
                p1 = fmaf(fmaxf(acc[t][2] + b0v, 0.0f), w0v, p1);
                p1 = fmaf(fmaxf(acc[t][3] + b1v, 0.0f), w1v, p1);
            }
            p0 += __shfl_xor_sync(0xffffffffu, p0, 1);
            p0 += __shfl_xor_sync(0xffffffffu, p0, 2);
            p1 += __shfl_xor_sync(0xffffffffu, p1, 1);
            p1 += __shfl_xor_sync(0xffffffffu, p1, 2);
            const int r = mt * 16 + (lane >> 2);
            if ((lane & 3) == 0) {
                sp[P_VBUF + nh * 64 + r]     = p0;
                sp[P_VBUF + nh * 64 + r + 8] = p1;
            }
            if (!nh) {   // gates: identical in both halves; one writer
                const int c = (lane & 3) * 2;
                sp[P_GBUF + r * 8 + c]           = acc[8][0];
                sp[P_GBUF + r * 8 + c + 1]       = acc[8][1];
                sp[P_GBUF + (r + 8) * 8 + c]     = acc[8][2];
                sp[P_GBUF + (r + 8) * 8 + c + 1] = acc[8][3];
            }
        }
        __syncthreads();

        // ---- tree epilogue: 1 thread per row ----
        if (tid < ROWS_BLK) {
            const int row = row0 + tid;
            const float* g = sp + P_GBUF + tid * 8;
            float g0 = g[0] + sp[P_B + 0];
            int n0 = (g0 >= 0.0f) ? 1 : 0;
            float g1 = g[1 + n0] + sp[P_B + 1 + n0];
            int n1 = n0 * 2 + ((g1 >= 0.0f) ? 1 : 0);
            float g2 = g[3 + n1] + sp[P_B + 3 + n1];
            int node = n1 * 2 + ((g2 >= 0.0f) ? 1 : 0);

            if (fminf(fminf(fabsf(g0), fabsf(g1)), fabsf(g2)) < 1e-3f) {
                // exact fp32 recompute of the path
                const float* xrow = x + (size_t)row * FEAT;
                g0 = sp[P_B + 0];
                for (int k = 0; k < FEAT; k++) g0 = fmaf(xrow[k], sp[P_W0 + k], g0);
                n0 = (g0 >= 0.0f) ? 1 : 0;
                {
                    const float* wr = sp + P_W1 + n0 * 133;
                    g1 = sp[P_B + 1 + n0];
                    for (int k = 0; k < 5; k++) g1 = fmaf(xrow[k], wr[k], g1);
                    const int off = 5 + n0 * 128;
                    for (int k = 0; k < 128; k++) g1 = fmaf(xrow[off + k], wr[5 + k], g1);
                }
                n1 = n0 * 2 + ((g1 >= 0.0f) ? 1 : 0);
                {
                    const float* wr = sp + P_W2 + n1 * 69;
                    g2 = sp[P_B + 3 + n1];
                    for (int k = 0; k < 5; k++) g2 = fmaf(xrow[k], wr[k], g2);
                    const int off = 5 + n1 * 64;
                    for (int k = 0; k < 64; k++) g2 = fmaf(xrow[off + k], wr[5 + k], g2);
                }
                node = n1 * 2 + ((g2 >= 0.0f) ? 1 : 0);
            }

            const float cum = sigmoidf_fast(g0) * sigmoidf_fast(g1) * sigmoidf_fast(g2);
            const float* lf = sp + P_LEAF + node * 8;
            float4 o0 = make_float4(cum*lf[0], cum*lf[1], cum*lf[2], cum*lf[3]);
            float4 o1 = make_float4(cum*lf[4], cum*lf[5], cum*lf[6], cum*lf[7]);
            ((float4*)(p_out + (size_t)row * 8))[0] = o0;
            ((float4*)(p_out + (size_t)row * 8))[1] = o1;
            v_out[row] = sp[P_VBUF + tid] + sp[P_VBUF + 64 + tid] + sp[P_B + 7];
        }
        __syncthreads();
    }
}

extern "C" void kernel_launch(void* const* d_in, const int* in_sizes, int n_in,
                              void* d_out, int out_size) {
    (void)in_sizes; (void)n_in; (void)out_size;
    const float* x    = (const float*)d_in[0];
    const float* w0   = (const float*)d_in[1];
    const float* b0   = (const float*)d_in[2];
    const float* w1   = (const float*)d_in[3];
    const float* b1   = (const float*)d_in[4];
    const float* w2   = (const float*)d_in[5];
    const float* b2   = (const float*)d_in[6];
    const float* leaf = (const float*)d_in[7];
    const float* Wc1  = (const float*)d_in[8];
    const float* bc1  = (const float*)d_in[9];
    const float* Wc2  = (const float*)d_in[10];
    const float* bc2  = (const float*)d_in[11];

    float* out   = (float*)d_out;
    float* p_out = out;
    float* v_out = out + (size_t)NB * 8;

    prep_w<<<(WFRAG_U32 + 255) / 256, 256>>>(Wc1, w0, w1, w2);

    cudaFuncSetAttribute(ac_main, cudaFuncAttributeMaxDynamicSharedMemorySize, SMEM_BYTES);
    ac_main<<<GRID, NTHREAD, SMEM_BYTES>>>(
        x, w0, b0, w1, b1, w2, b2, leaf, bc1, Wc2, bc2, p_out, v_out);
}

// round 7
// speedup vs baseline: 1.3340x; 1.3340x over previous
#include <cuda_runtime.h>
#include <cuda_bf16.h>
#include <cstdint>

#define NB 65536
#define FEAT 261
#define HID 128
#define KSTEPS 17                  // K padded to 272
#define NTILES 17                  // 136 cols: 128 Wc1 + 7 gates + 1 pad
#define NTHREAD 512
#define ROWS_CTA 256
#define NCTA (NB / ROWS_CTA)       // 256

// W fragment scratch: [kstep][tile][lane][4 u32 = bh0,bh1,bl0,bl1]
#define WFRAG_U32 (KSTEPS * NTILES * 32 * 4)   // 36992 u32 = 147968 B
__device__ __align__(16) uint32_t g_wfrag[WFRAG_U32];

// ---- smem param layout (floats) ----
#define P_W0   0      // 288
#define P_W1   288    // 268 (266 used)
#define P_W2   556    // 276
#define P_LEAF 832    // 64
#define P_BC1  896    // 128
#define P_WC2  1024   // 128
#define P_B    1152   // b0, b1[2], b2[4], bc2
#define P_VBUF 1160   // 2 x 256
#define P_GBUF 1672   // 256 x 8
#define PARAM_FLOATS 3720
#define OFF_WF (PARAM_FLOATS * 4)                  // 14880 (16B aligned)
#define SMEM_BYTES (OFF_WF + WFRAG_U32 * 4)        // 162848

// ======================= prep: extended W -> interleaved bf16 hi/lo fragments =======================
__device__ __forceinline__ float wgate_val(int j, int k, const float* w0,
                                           const float* w1, const float* w2) {
    if (k >= FEAT) return 0.0f;
    if (j == 0) return w0[k];
    if (j < 3) {
        int nd = j - 1;
        if (k < 5) return w1[nd * 133 + k];
        int lo = 5 + nd * 128;
        if (k >= lo && k < lo + 128) return w1[nd * 133 + 5 + (k - lo)];
        return 0.0f;
    }
    if (j < 7) {
        int nd = j - 3;
        if (k < 5) return w2[nd * 69 + k];
        int lo = 5 + nd * 64;
        if (k >= lo && k < lo + 64) return w2[nd * 69 + 5 + (k - lo)];
        return 0.0f;
    }
    return 0.0f;
}

__global__ void __launch_bounds__(256) prep_w(const float* __restrict__ Wc1,
                                              const float* __restrict__ w0,
                                              const float* __restrict__ w1,
                                              const float* __restrict__ w2) {
    int idx = blockIdx.x * 256 + threadIdx.x;
    if (idx >= WFRAG_U32) return;
    int j    = idx & 3;            // 0,1: hi (b0,b1); 2,3: lo (b0,b1)
    int lane = (idx >> 2) & 31;
    int tt   = (idx >> 7) % NTILES;
    int s    = (idx >> 7) / NTILES;
    int n = tt * 8 + (lane >> 2);
    int k = s * 16 + (j & 1) * 8 + (lane & 3) * 2;

    float v0, v1;
    if (n < HID) {
        v0 = (k     < FEAT) ? Wc1[k * HID + n]       : 0.0f;
        v1 = (k + 1 < FEAT) ? Wc1[(k + 1) * HID + n] : 0.0f;
    } else {
        int jc = n - HID;
        v0 = wgate_val(jc, k,     w0, w1, w2);
        v1 = wgate_val(jc, k + 1, w0, w1, w2);
    }
    __nv_bfloat16 h0 = __float2bfloat16(v0), h1 = __float2bfloat16(v1);
    if (j < 2) {
        g_wfrag[idx] = ((uint32_t)__bfloat16_as_ushort(h1) << 16) | __bfloat16_as_ushort(h0);
    } else {
        __nv_bfloat16 l0 = __float2bfloat16(v0 - __bfloat162float(h0));
        __nv_bfloat16 l1 = __float2bfloat16(v1 - __bfloat162float(h1));
        g_wfrag[idx] = ((uint32_t)__bfloat16_as_ushort(l1) << 16) | __bfloat16_as_ushort(l0);
    }
}

// ======================= helpers =======================
__device__ __forceinline__ float sigmoidf_fast(float g) { return 1.0f / (1.0f + __expf(-g)); }

__device__ __forceinline__ uint32_t split_pair(float v0, float v1, uint32_t& lo) {
    uint32_t b0 = __float_as_uint(v0), b1 = __float_as_uint(v1), hi;
    asm("prmt.b32 %0, %1, %2, 0x7632;" : "=r"(hi) : "r"(b0), "r"(b1));
    float t0 = __uint_as_float(b0 & 0xFFFF0000u);
    float t1 = __uint_as_float(b1 & 0xFFFF0000u);
    float l0 = v0 - t0, l1 = v1 - t1;
    asm("cvt.rn.bf16x2.f32 %0, %1, %2;" : "=r"(lo) : "f"(l1), "f"(l0));
    return hi;
}

#define MMA16816(c, a0, a1, a2, a3, b0, b1) \
    asm volatile("mma.sync.aligned.m16n8k16.row.col.f32.bf16.bf16.f32 " \
        "{%0,%1,%2,%3}, {%4,%5,%6,%7}, {%8,%9}, {%0,%1,%2,%3};" \
        : "+f"((c)[0]), "+f"((c)[1]), "+f"((c)[2]), "+f"((c)[3]) \
        : "r"(a0), "r"(a1), "r"(a2), "r"(a3), "r"(b0), "r"(b1))

// ======================= main fused kernel =======================
__global__ void __launch_bounds__(NTHREAD, 1)
ac_main(const float* __restrict__ x,
        const float* __restrict__ w0, const float* __restrict__ b0,
        const float* __restrict__ w1, const float* __restrict__ b1,
        const float* __restrict__ w2, const float* __restrict__ b2,
        const float* __restrict__ leaf,
        const float* __restrict__ bc1,
        const float* __restrict__ Wc2, const float* __restrict__ bc2,
        float* __restrict__ p_out, float* __restrict__ v_out)
{
    extern __shared__ char smem[];
    float* sp = (float*)smem;
    const int tid  = threadIdx.x;
    const int lane = tid & 31;
    const int warp = tid >> 5;
    const int mt   = warp >> 1;     // m-tile 0..7 (32 rows each)
    const int nh   = warp & 1;      // n-half
    const int row0 = blockIdx.x * ROWS_CTA;

    // ---- stage params + W fragments ----
    for (int i = tid; i < 288; i += NTHREAD) sp[P_W0 + i] = (i < FEAT) ? w0[i] : 0.0f;
    for (int i = tid; i < 266; i += NTHREAD) sp[P_W1 + i] = w1[i];
    for (int i = tid; i < 276; i += NTHREAD) sp[P_W2 + i] = w2[i];
    if (tid < 64)  sp[P_LEAF + tid] = leaf[tid];
    if (tid < 128) sp[P_BC1 + tid]  = bc1[tid];
    if (tid < 128) sp[P_WC2 + tid]  = Wc2[tid];
    if (tid == 0) {
        sp[P_B + 0] = b0[0];
        sp[P_B + 1] = b1[0]; sp[P_B + 2] = b1[1];
        sp[P_B + 3] = b2[0]; sp[P_B + 4] = b2[1]; sp[P_B + 5] = b2[2]; sp[P_B + 6] = b2[3];
        sp[P_B + 7] = bc2[0];
    }
    {
        const uint4* g = (const uint4*)g_wfrag;
        uint4* s = (uint4*)(smem + OFF_WF);
        #pragma unroll 4
        for (int i = tid; i < WFRAG_U32 / 4; i += NTHREAD) s[i] = g[i];
    }
    __syncthreads();

    // ================= fused GEMM: warp = m32 x n64 (+ gate tile for its m-sub) =================
    const float* xr  = x + (size_t)(row0 + mt * 32 + (lane >> 2)) * FEAT;
    const float* xr8 = xr + (size_t)8 * FEAT;
    const int kb = (lane & 3) * 2;

    float acc[2][8][4];
    float accg[4];
    #pragma unroll
    for (int m = 0; m < 2; m++)
        #pragma unroll
        for (int t = 0; t < 8; t++)
            #pragma unroll
            for (int j = 0; j < 4; j++) acc[m][t][j] = 0.0f;
    #pragma unroll
    for (int j = 0; j < 4; j++) accg[j] = 0.0f;

    auto load_a = [&](float* af, int s, bool guard) {
        const int k0 = s * 16 + kb;
        #pragma unroll
        for (int m = 0; m < 2; m++) {
            const float* a = xr  + (size_t)(m * 16) * FEAT;
            const float* b = xr8 + (size_t)(m * 16) * FEAT;
            if (!guard) {
                af[m*8+0] = a[k0];   af[m*8+1] = a[k0+1];
                af[m*8+2] = b[k0];   af[m*8+3] = b[k0+1];
                af[m*8+4] = a[k0+8]; af[m*8+5] = a[k0+9];
                af[m*8+6] = b[k0+8]; af[m*8+7] = b[k0+9];
            } else {
                af[m*8+0] = (k0   < FEAT) ? a[k0]   : 0.0f;
                af[m*8+1] = (k0+1 < FEAT) ? a[k0+1] : 0.0f;
                af[m*8+2] = (k0   < FEAT) ? b[k0]   : 0.0f;
                af[m*8+3] = (k0+1 < FEAT) ? b[k0+1] : 0.0f;
                af[m*8+4] = (k0+8 < FEAT) ? a[k0+8] : 0.0f;
                af[m*8+5] = (k0+9 < FEAT) ? a[k0+9] : 0.0f;
                af[m*8+6] = (k0+8 < FEAT) ? b[k0+8] : 0.0f;
                af[m*8+7] = (k0+9 < FEAT) ? b[k0+9] : 0.0f;
            }
        }
    };

    uint32_t ah[2][4], al[2][4];
    {
        float af[16];
        load_a(af, 0, false);
        #pragma unroll
        for (int m = 0; m < 2; m++)
            #pragma unroll
            for (int p = 0; p < 4; p++)
                ah[m][p] = split_pair(af[m*8 + p*2], af[m*8 + p*2 + 1], al[m][p]);
    }

    const uint4* wf = (const uint4*)(smem + OFF_WF);

    #pragma unroll 1
    for (int s = 0; s < KSTEPS; s++) {
        float afn[16];
        if (s < KSTEPS - 1) load_a(afn, s + 1, s + 1 == KSTEPS - 1);

        const uint4* bp = wf + ((s * NTILES + nh * 8) * 32 + lane);
        #pragma unroll
        for (int t = 0; t < 8; t++) {
            const uint4 b = bp[t * 32];
            #pragma unroll
            for (int m = 0; m < 2; m++) {
                MMA16816(acc[m][t], ah[m][0], ah[m][1], ah[m][2], ah[m][3], b.x, b.y);
                MMA16816(acc[m][t], al[m][0], al[m][1], al[m][2], al[m][3], b.x, b.y);
                MMA16816(acc[m][t], ah[m][0], ah[m][1], ah[m][2], ah[m][3], b.z, b.w);
            }
        }
        {   // gate tile: this warp handles m-subtile == nh
            const uint4 b = wf[(s * NTILES + 16) * 32 + lane];
            MMA16816(accg, ah[nh][0], ah[nh][1], ah[nh][2], ah[nh][3], b.x, b.y);
            MMA16816(accg, al[nh][0], al[nh][1], al[nh][2], al[nh][3], b.x, b.y);
            MMA16816(accg, ah[nh][0], ah[nh][1], ah[nh][2], ah[nh][3], b.z, b.w);
        }

        if (s < KSTEPS - 1) {
            #pragma unroll
            for (int p = 0; p < 4; p++) {
                ah[0][p] = split_pair(afn[p*2],     afn[p*2 + 1],     al[0][p]);
                ah[1][p] = split_pair(afn[8 + p*2], afn[8 + p*2 + 1], al[1][p]);
            }
        }
    }

    // ---- GEMM epilogue: v partials + gate buffer ----
    #pragma unroll
    for (int m = 0; m < 2; m++) {
        float p0 = 0.0f, p1 = 0.0f;
        #pragma unroll
        for (int t = 0; t < 8; t++) {
            const int c0 = nh * 64 + t * 8 + (lane & 3) * 2;
            const float b0v = sp[P_BC1 + c0],     w0v = sp[P_WC2 + c0];
            const float b1v = sp[P_BC1 + c0 + 1], w1v = sp[P_WC2 + c0 + 1];
            p0 = fmaf(fmaxf(acc[m][t][0] + b0v, 0.0f), w0v, p0);
            p0 = fmaf(fmaxf(acc[m][t][1] + b1v, 0.0f), w1v, p0);
            p1 = fmaf(fmaxf(acc[m][t][2] + b0v, 0.0f), w0v, p1);
            p1 = fmaf(fmaxf(acc[m][t][3] + b1v, 0.0f), w1v, p1);
        }
        p0 += __shfl_xor_sync(0xffffffffu, p0, 1);
        p0 += __shfl_xor_sync(0xffffffffu, p0, 2);
        p1 += __shfl_xor_sync(0xffffffffu, p1, 1);
        p1 += __shfl_xor_sync(0xffffffffu, p1, 2);
        if ((lane & 3) == 0) {
            const int r = mt * 32 + m * 16 + (lane >> 2);
            sp[P_VBUF + nh * 256 + r]     = p0;
            sp[P_VBUF + nh * 256 + r + 8] = p1;
        }
    }
    {   // gates for m-subtile nh
        const int r = mt * 32 + nh * 16 + (lane >> 2);
        const int c = (lane & 3) * 2;
        sp[P_GBUF + r * 8 + c]           = accg[0];
        sp[P_GBUF + r * 8 + c + 1]       = accg[1];
        sp[P_GBUF + (r + 8) * 8 + c]     = accg[2];
        sp[P_GBUF + (r + 8) * 8 + c + 1] = accg[3];
    }
    __syncthreads();

    // ---- tree epilogue: 1 thread per row ----
    if (tid < ROWS_CTA) {
        const int row = row0 + tid;
        const float* g = sp + P_GBUF + tid * 8;
        float g0 = g[0] + sp[P_B + 0];
        int n0 = (g0 >= 0.0f) ? 1 : 0;
        float g1 = g[1 + n0] + sp[P_B + 1 + n0];
        int n1 = n0 * 2 + ((g1 >= 0.0f) ? 1 : 0);
        float g2 = g[3 + n1] + sp[P_B + 3 + n1];
        int node = n1 * 2 + ((g2 >= 0.0f) ? 1 : 0);

        if (fminf(fminf(fabsf(g0), fabsf(g1)), fabsf(g2)) < 1e-3f) {
            // exact fp32 recompute of the path (rare)
            const float* xrow = x + (size_t)row * FEAT;
            g0 = sp[P_B + 0];
            for (int k = 0; k < FEAT; k++) g0 = fmaf(xrow[k], sp[P_W0 + k], g0);
            n0 = (g0 >= 0.0f) ? 1 : 0;
            {
                const float* wr = sp + P_W1 + n0 * 133;
                g1 = sp[P_B + 1 + n0];
                for (int k = 0; k < 5; k++) g1 = fmaf(xrow[k], wr[k], g1);
                const int off = 5 + n0 * 128;
                for (int k = 0; k < 128; k++) g1 = fmaf(xrow[off + k], wr[5 + k], g1);
            }
            n1 = n0 * 2 + ((g1 >= 0.0f) ? 1 : 0);
            {
                const float* wr = sp + P_W2 + n1 * 69;
                g2 = sp[P_B + 3 + n1];
                for (int k = 0; k < 5; k++) g2 = fmaf(xrow[k], wr[k], g2);
                const int off = 5 + n1 * 64;
                for (int k = 0; k < 64; k++) g2 = fmaf(xrow[off + k], wr[5 + k], g2);
            }
            node = n1 * 2 + ((g2 >= 0.0f) ? 1 : 0);
        }

        const float cum = sigmoidf_fast(g0) * sigmoidf_fast(g1) * sigmoidf_fast(g2);
        const float* lf = sp + P_LEAF + node * 8;
        float4 o0 = make_float4(cum*lf[0], cum*lf[1], cum*lf[2], cum*lf[3]);
        float4 o1 = make_float4(cum*lf[4], cum*lf[5], cum*lf[6], cum*lf[7]);
        ((float4*)(p_out + (size_t)row * 8))[0] = o0;
        ((float4*)(p_out + (size_t)row * 8))[1] = o1;
        v_out[row] = sp[P_VBUF + tid] + sp[P_VBUF + 256 + tid] + sp[P_B + 7];
    }
}

extern "C" void kernel_launch(void* const* d_in, const int* in_sizes, int n_in,
                              void* d_out, int out_size) {
    (void)in_sizes; (void)n_in; (void)out_size;
    const float* x    = (const float*)d_in[0];
    const float* w0   = (const float*)d_in[1];
    const float* b0   = (const float*)d_in[2];
    const float* w1   = (const float*)d_in[3];
    const float* b1   = (const float*)d_in[4];
    const float* w2   = (const float*)d_in[5];
    const float* b2   = (const float*)d_in[6];
    const float* leaf = (const float*)d_in[7];
    const float* Wc1  = (const float*)d_in[8];
    const float* bc1  = (const float*)d_in[9];
    const float* Wc2  = (const float*)d_in[10];
    const float* bc2  = (const float*)d_in[11];

    float* out   = (float*)d_out;
    float* p_out = out;
    float* v_out = out + (size_t)NB * 8;

    prep_w<<<(WFRAG_U32 + 255) / 256, 256>>>(Wc1, w0, w1, w2);

    cudaFuncSetAttribute(ac_main, cudaFuncAttributeMaxDynamicSharedMemorySize, SMEM_BYTES);
    ac_main<<<NCTA, NTHREAD, SMEM_BYTES>>>(
        x, w0, b0, w1, b1, w2, b2, leaf, bc1, Wc2, bc2, p_out, v_out);
}